// round 4
// baseline (speedup 1.0000x reference)
#include <cuda_runtime.h>
#include <cuda_bf16.h>
#include <cstdint>

#define NN 8192
#define INF 512
#define OF 128

// ---------------- scratch (device globals; no allocation) ----------------
__device__ __nv_bfloat16 g_WhT[(size_t)OF * NN];   // [feat][node] bf16
__device__ float g_Wh1[NN];
__device__ float g_Wh2[NN];
__device__ float g_num[(size_t)2 * NN * OF];       // [split][node][feat]
__device__ float g_den[2 * NN];                    // [split][node]

// ---------------- helpers ----------------
__device__ __forceinline__ uint32_t pack2(float lo, float hi) {
    uint32_t r;
    asm("cvt.rn.bf16x2.f32 %0, %1, %2;" : "=r"(r) : "f"(hi), "f"(lo));
    return r;
}
__device__ __forceinline__ void sts64(uint32_t a, uint32_t x, uint32_t y) {
    asm volatile("st.shared.v2.b32 [%0], {%1,%2};" :: "r"(a), "r"(x), "r"(y) : "memory");
}
__device__ __forceinline__ void sts32f(uint32_t a, float v) {
    asm volatile("st.shared.f32 [%0], %1;" :: "r"(a), "f"(v) : "memory");
}
__device__ __forceinline__ float lds32f(uint32_t a) {
    float v; asm volatile("ld.shared.f32 %0, [%1];" : "=f"(v) : "r"(a)); return v;
}
__device__ __forceinline__ float4 lds128f(uint32_t a) {
    float4 v;
    asm volatile("ld.shared.v4.f32 {%0,%1,%2,%3}, [%4];"
                 : "=f"(v.x), "=f"(v.y), "=f"(v.z), "=f"(v.w) : "r"(a));
    return v;
}
__device__ __forceinline__ int4 lds128i(uint32_t a) {
    int4 v;
    asm volatile("ld.shared.v4.b32 {%0,%1,%2,%3}, [%4];"
                 : "=r"(v.x), "=r"(v.y), "=r"(v.z), "=r"(v.w) : "r"(a));
    return v;
}
__device__ __forceinline__ void ldsm4(uint32_t* r, uint32_t a) {
    asm volatile("ldmatrix.sync.aligned.m8n8.x4.shared.b16 {%0,%1,%2,%3}, [%4];"
                 : "=r"(r[0]), "=r"(r[1]), "=r"(r[2]), "=r"(r[3]) : "r"(a));
}
__device__ __forceinline__ void mma16816(float* d, const uint32_t* a, uint32_t b0, uint32_t b1) {
    asm volatile(
        "mma.sync.aligned.m16n8k16.row.col.f32.bf16.bf16.f32 "
        "{%0,%1,%2,%3}, {%4,%5,%6,%7}, {%8,%9}, {%0,%1,%2,%3};"
        : "+f"(d[0]), "+f"(d[1]), "+f"(d[2]), "+f"(d[3])
        : "r"(a[0]), "r"(a[1]), "r"(a[2]), "r"(a[3]), "r"(b0), "r"(b1));
}
__device__ __forceinline__ void cp16(uint32_t s, const void* g) {
    asm volatile("cp.async.cg.shared.global [%0], [%1], 16;" :: "r"(s), "l"(g) : "memory");
}

// ================= K1: Wh = h @ W (fp32 FFMA), WhT bf16 + Wh1/Wh2 =================
// 128 CTAs x 64 rows.
__global__ __launch_bounds__(256) void k_gemm(const float* __restrict__ h,
                                              const float* __restrict__ W,
                                              const float* __restrict__ a) {
    __shared__ float sh_h[64 * 16];
    __shared__ float sh_w[16 * 128];
    __shared__ float red[2 * 64 * 16];

    const int t  = threadIdx.x;
    const int tx = t & 15, ty = t >> 4;
    const int i0 = blockIdx.x * 64;

    float acc[4][8];
#pragma unroll
    for (int r = 0; r < 4; r++)
#pragma unroll
        for (int c = 0; c < 8; c++) acc[r][c] = 0.f;

    float a1c[8], a2c[8];
#pragma unroll
    for (int c = 0; c < 8; c++) { a1c[c] = a[tx * 8 + c]; a2c[c] = a[OF + tx * 8 + c]; }

    for (int k0 = 0; k0 < INF; k0 += 16) {
        {   // h tile 64x16 = 256 float4
            int r = t >> 2, c4 = t & 3;
            float4 v = *reinterpret_cast<const float4*>(&h[(size_t)(i0 + r) * INF + k0 + c4 * 4]);
            *reinterpret_cast<float4*>(&sh_h[r * 16 + c4 * 4]) = v;
        }
#pragma unroll
        for (int ll = 0; ll < 2; ll++) {   // W tile 16x128 = 512 float4
            int idx = t + ll * 256;
            int r = idx >> 5, c4 = idx & 31;
            float4 v = *reinterpret_cast<const float4*>(&W[(size_t)(k0 + r) * OF + c4 * 4]);
            *reinterpret_cast<float4*>(&sh_w[r * OF + c4 * 4]) = v;
        }
        __syncthreads();
#pragma unroll
        for (int kk = 0; kk < 16; kk++) {
            float av[4], bv[8];
#pragma unroll
            for (int r = 0; r < 4; r++) av[r] = sh_h[(ty * 4 + r) * 16 + kk];
#pragma unroll
            for (int c = 0; c < 8; c++) bv[c] = sh_w[kk * OF + tx * 8 + c];
#pragma unroll
            for (int r = 0; r < 4; r++)
#pragma unroll
                for (int c = 0; c < 8; c++) acc[r][c] = fmaf(av[r], bv[c], acc[r][c]);
        }
        __syncthreads();
    }

#pragma unroll
    for (int r = 0; r < 4; r++) {
        int i = i0 + ty * 4 + r;
        float p1 = 0.f, p2 = 0.f;
#pragma unroll
        for (int c = 0; c < 8; c++) {
            float v = acc[r][c];
            g_WhT[(size_t)(tx * 8 + c) * NN + i] = __float2bfloat16(v);
            p1 = fmaf(v, a1c[c], p1);
            p2 = fmaf(v, a2c[c], p2);
        }
        red[(ty * 4 + r) * 16 + tx] = p1;
        red[1024 + (ty * 4 + r) * 16 + tx] = p2;
    }
    __syncthreads();
    if (t < 64) {
        float s1 = 0.f, s2 = 0.f;
#pragma unroll
        for (int x = 0; x < 16; x++) { s1 += red[t * 16 + x]; s2 += red[1024 + t * 16 + x]; }
        g_Wh1[i0 + t] = s1;
        g_Wh2[i0 + t] = s2;
    }
}

// ================= K2: fused masked-softmax attention via mma.sync =================
// CTA: 128 rows x 4096 j (split in 2). Per 128-j tile: build P bf16 (swizzled),
// cp.async-staged adj + double-buffered WhT B tile, warp-level bf16 MMA.

#define SP    0u
#define SB0   32768u
#define SADJ  98304u
#define SWH2  163840u
#define SWH1  180224u
#define SM_DYN (180736 + 128)

__device__ __forceinline__ void issue_tile(uint32_t sb, const int* adjg,
                                           const __nv_bfloat16* whg, int t, int tt) {
    // B (WhT) tile: 128 feats x 128 j bf16, swizzled blocked-atom layout
    const int bf = t >> 1, bh = t & 1;
    const uint32_t bbase = sb + SB0 + (uint32_t)(tt & 1) * 32768u
        + (uint32_t)((bf >> 3) + bh * 16) * 1024u + (uint32_t)(bf & 7) * 128u;
    const uint32_t bkey = (uint32_t)(bf & 7) << 4;
    const __nv_bfloat16* bs = whg + (size_t)bf * NN + tt * 128 + bh * 64;
#pragma unroll
    for (int c = 0; c < 8; c++)
        cp16(bbase + (((uint32_t)c * 16u) ^ bkey), bs + c * 8);
    // adj tile: 128 rows x 128 ints, row-swizzled
#pragma unroll
    for (int i2 = 0; i2 < 16; i2++) {
        int c = t + i2 * 256;
        int row = c >> 5, q = c & 31;
        cp16(sb + SADJ + (uint32_t)row * 512u + (((uint32_t)q * 16u) ^ ((uint32_t)(row & 7) << 4)),
             adjg + (size_t)row * NN + tt * 128 + q * 4);
    }
    asm volatile("cp.async.commit_group;" ::: "memory");
}

__global__ void __launch_bounds__(256, 1) k_attn(const int* __restrict__ adj) {
    extern __shared__ char dsm[];
    uint32_t sb = (uint32_t)__cvta_generic_to_shared(dsm);
    sb = (sb + 127u) & ~127u;

    const int t = threadIdx.x, w = t >> 5, l = t & 31;
    const int rb = blockIdx.x >> 1, split = blockIdx.x & 1;
    const int i0 = rb * 128, jb = split * 4096;

    const int* adjg = adj + (size_t)i0 * NN + jb;
    const __nv_bfloat16* whg = g_WhT + jb;

    // stage Wh2 (4096) + Wh1 (128)
    for (int x = t; x < 4096; x += 256) sts32f(sb + SWH2 + (uint32_t)x * 4u, g_Wh2[jb + x]);
    if (t < 128) sts32f(sb + SWH1 + (uint32_t)t * 4u, g_Wh1[i0 + t]);

    issue_tile(sb, adjg, whg, t, 0);

    // MMA per-thread constants: warp tile m0=rows, n0=feats
    const int m0 = (w >> 1) * 32, n0 = (w & 1) * 64;
    const int q = l >> 3, lq = l & 7;
    const int arow = m0 + (q & 1) * 8 + lq;
    const int acolb = (q >> 1) * 8;
    const uint32_t paA = ((uint32_t)(arow >> 3) << 10) + ((uint32_t)(arow & 7) << 7);
    const uint32_t keyA = (uint32_t)(arow & 7) << 4;
    const int bfeat = n0 + (q >> 1) * 8 + lq;
    const int bcolb = (q & 1) * 8;
    const uint32_t paB = ((uint32_t)(bfeat >> 3) << 10) + ((uint32_t)(bfeat & 7) << 7);
    const uint32_t keyB = (uint32_t)(bfeat & 7) << 4;

    float acc[2][8][4];
#pragma unroll
    for (int mt = 0; mt < 2; mt++)
#pragma unroll
        for (int nt = 0; nt < 8; nt++)
#pragma unroll
            for (int c = 0; c < 4; c++) acc[mt][nt][c] = 0.f;
    float dden[16];
#pragma unroll
    for (int r = 0; r < 16; r++) dden[r] = 0.f;

#pragma unroll 1
    for (int tt = 0; tt < 32; tt++) {
        asm volatile("cp.async.wait_group 0;" ::: "memory");
        __syncthreads();   // adj/B visible; P free from previous mma

        // ---- build P tile: warp w builds rows w*16..+15, lane covers 4 j ----
        {
            float4 w2 = lds128f(sb + SWH2 + (uint32_t)(tt * 128 + l * 4) * 4u);
#pragma unroll
            for (int r = 0; r < 16; r++) {
                int row = (w << 4) + r;
                float wh1v = lds32f(sb + SWH1 + (uint32_t)row * 4u);
                int4 a4 = lds128i(sb + SADJ + (uint32_t)row * 512u
                                  + (((uint32_t)l * 16u) ^ ((uint32_t)(row & 7) << 4)));
                float x0 = wh1v + w2.x, x1 = wh1v + w2.y, x2 = wh1v + w2.z, x3 = wh1v + w2.w;
                float p0 = a4.x ? __expf(fmaxf(x0, 0.2f * x0)) : 0.f;
                float p1 = a4.y ? __expf(fmaxf(x1, 0.2f * x1)) : 0.f;
                float p2 = a4.z ? __expf(fmaxf(x2, 0.2f * x2)) : 0.f;
                float p3 = a4.w ? __expf(fmaxf(x3, 0.2f * x3)) : 0.f;
                dden[r] += (p0 + p1) + (p2 + p3);
                uint32_t paddr = sb + SP
                    + (uint32_t)(((row >> 3) + ((l >> 4) << 4)) * 1024 + (row & 7) * 128)
                    + (((uint32_t)(l & 15) * 8u) ^ ((uint32_t)(row & 7) << 4));
                sts64(paddr, pack2(p0, p1), pack2(p2, p3));
            }
        }
        __syncthreads();   // P visible; adj stage consumed

        if (tt < 31) issue_tile(sb, adjg, whg, t, tt + 1);

        // ---- mma phase ----
        {
            const uint32_t sB = sb + SB0 + (uint32_t)(tt & 1) * 32768u;
#pragma unroll
            for (int kk = 0; kk < 8; kk++) {
                int colA = kk * 16 + acolb;
                uint32_t aA = sb + SP + paA + (uint32_t)((colA >> 6) << 14)
                            + ((uint32_t)((colA & 63) << 1) ^ keyA);
                uint32_t af0[4], af1[4];
                ldsm4(af0, aA);
                ldsm4(af1, aA + 2048u);
                int colB = kk * 16 + bcolb;
                uint32_t aB = sB + paB + (uint32_t)((colB >> 6) << 14)
                            + ((uint32_t)((colB & 63) << 1) ^ keyB);
                uint32_t bfr[4][4];
                ldsm4(bfr[0], aB);
                ldsm4(bfr[1], aB + 2048u);
                ldsm4(bfr[2], aB + 4096u);
                ldsm4(bfr[3], aB + 6144u);
#pragma unroll
                for (int nt = 0; nt < 8; nt++) {
                    uint32_t b0 = bfr[nt >> 1][(nt & 1) * 2];
                    uint32_t b1 = bfr[nt >> 1][(nt & 1) * 2 + 1];
                    mma16816(acc[0][nt], af0, b0, b1);
                    mma16816(acc[1][nt], af1, b0, b1);
                }
            }
        }
    }

    // ---- den: reduce lanes per build-row ----
#pragma unroll
    for (int r = 0; r < 16; r++) {
        float v = dden[r];
        v += __shfl_xor_sync(0xffffffffu, v, 16);
        v += __shfl_xor_sync(0xffffffffu, v, 8);
        v += __shfl_xor_sync(0xffffffffu, v, 4);
        v += __shfl_xor_sync(0xffffffffu, v, 2);
        v += __shfl_xor_sync(0xffffffffu, v, 1);
        if (l == 0) g_den[split * NN + i0 + (w << 4) + r] = v;
    }

    // ---- num epilogue ----
#pragma unroll
    for (int mt = 0; mt < 2; mt++)
#pragma unroll
        for (int nt = 0; nt < 8; nt++) {
            int row = i0 + m0 + mt * 16 + (l >> 2);
            int feat = n0 + nt * 8 + (l & 3) * 2;
            float* b = &g_num[((size_t)split * NN + row) * OF + feat];
            b[0] = acc[mt][nt][0];
            b[1] = acc[mt][nt][1];
            b[8 * OF] = acc[mt][nt][2];
            b[8 * OF + 1] = acc[mt][nt][3];
        }
}

// ================= K3: combine splits, finalize =================
__global__ __launch_bounds__(256) void k_final(const float* __restrict__ rnd,
                                               float* __restrict__ out) {
    int idx = blockIdx.x * 256 + threadIdx.x;
    int i = idx >> 7;
    float num = g_num[idx] + g_num[(size_t)NN * OF + idx];
    float den = g_den[i] + g_den[NN + i];
    float v = (num / den + rnd[idx]) * 1e-5f;
    out[idx] = v > 0.f ? v : expm1f(v);
}

// ================= launch =================
extern "C" void kernel_launch(void* const* d_in, const int* in_sizes, int n_in,
                              void* d_out, int out_size) {
    const float* h   = (const float*)d_in[0];
    const int*   adj = (const int*)d_in[1];
    const float* W   = (const float*)d_in[2];
    const float* a   = (const float*)d_in[3];
    const float* rnd = (const float*)d_in[4];
    float* out = (float*)d_out;

    cudaFuncSetAttribute(k_attn, cudaFuncAttributeMaxDynamicSharedMemorySize, SM_DYN);

    k_gemm<<<128, 256>>>(h, W, a);
    k_attn<<<128, 256, SM_DYN>>>(adj);
    k_final<<<4096, 256>>>(rnd, out);
}

// round 5
// speedup vs baseline: 1.2067x; 1.2067x over previous
#include <cuda_runtime.h>
#include <cuda_bf16.h>
#include <cstdint>

#define NN 8192
#define INF 512
#define OF 128

// ---------------- scratch (device globals; no allocation) ----------------
__device__ __nv_bfloat16 g_hb[(size_t)NN * INF];   // h in bf16 [node][k]
__device__ __nv_bfloat16 g_WT[(size_t)OF * INF];   // W^T bf16 [feat][k]
__device__ __nv_bfloat16 g_WhT[(size_t)OF * NN];   // [feat][node] bf16
__device__ float g_Wh1[NN];
__device__ float g_Wh2[NN];
__device__ float g_num[(size_t)2 * NN * OF];       // [split][node][feat]
__device__ float g_den[2 * NN];                    // [split][node]

// ---------------- helpers ----------------
__device__ __forceinline__ uint32_t pack2(float lo, float hi) {
    uint32_t r;
    asm("cvt.rn.bf16x2.f32 %0, %1, %2;" : "=r"(r) : "f"(hi), "f"(lo));
    return r;
}
__device__ __forceinline__ void sts64(uint32_t a, uint32_t x, uint32_t y) {
    asm volatile("st.shared.v2.b32 [%0], {%1,%2};" :: "r"(a), "r"(x), "r"(y) : "memory");
}
__device__ __forceinline__ void sts32f(uint32_t a, float v) {
    asm volatile("st.shared.f32 [%0], %1;" :: "r"(a), "f"(v) : "memory");
}
__device__ __forceinline__ float lds32f(uint32_t a) {
    float v; asm volatile("ld.shared.f32 %0, [%1];" : "=f"(v) : "r"(a)); return v;
}
__device__ __forceinline__ float4 lds128f(uint32_t a) {
    float4 v;
    asm volatile("ld.shared.v4.f32 {%0,%1,%2,%3}, [%4];"
                 : "=f"(v.x), "=f"(v.y), "=f"(v.z), "=f"(v.w) : "r"(a));
    return v;
}
__device__ __forceinline__ void ldsm4(uint32_t* r, uint32_t a) {
    asm volatile("ldmatrix.sync.aligned.m8n8.x4.shared.b16 {%0,%1,%2,%3}, [%4];"
                 : "=r"(r[0]), "=r"(r[1]), "=r"(r[2]), "=r"(r[3]) : "r"(a));
}
__device__ __forceinline__ void mma16816(float* d, const uint32_t* a, uint32_t b0, uint32_t b1) {
    asm volatile(
        "mma.sync.aligned.m16n8k16.row.col.f32.bf16.bf16.f32 "
        "{%0,%1,%2,%3}, {%4,%5,%6,%7}, {%8,%9}, {%0,%1,%2,%3};"
        : "+f"(d[0]), "+f"(d[1]), "+f"(d[2]), "+f"(d[3])
        : "r"(a[0]), "r"(a[1]), "r"(a[2]), "r"(a[3]), "r"(b0), "r"(b1));
}
__device__ __forceinline__ void cp16(uint32_t s, const void* g) {
    asm volatile("cp.async.cg.shared.global [%0], [%1], 16;" :: "r"(s), "l"(g) : "memory");
}

// ================= K0: prep — h->bf16, W->W^T bf16, zero Wh1/Wh2 =================
__global__ __launch_bounds__(256) void k_prep(const float* __restrict__ h,
                                              const float* __restrict__ W) {
    const int b = blockIdx.x, t = threadIdx.x;
    if (b < 1024) {                    // h convert: 1024 CTAs x 1024 float4
#pragma unroll
        for (int u = 0; u < 4; u++) {
            size_t i4 = (size_t)b * 1024 + u * 256 + t;
            float4 v = reinterpret_cast<const float4*>(h)[i4];
            uint2 p = make_uint2(pack2(v.x, v.y), pack2(v.z, v.w));
            *reinterpret_cast<uint2*>(&g_hb[i4 * 4]) = p;
        }
    } else if (b < 1088) {             // W transpose: 64 CTAs x 1024 elems
        int idx = (b - 1024) * 1024 + t * 4;
        int k = idx >> 7, f = idx & 127;
        float4 v = *reinterpret_cast<const float4*>(&W[(size_t)k * OF + f]);
        g_WT[(size_t)(f + 0) * INF + k] = __float2bfloat16(v.x);
        g_WT[(size_t)(f + 1) * INF + k] = __float2bfloat16(v.y);
        g_WT[(size_t)(f + 2) * INF + k] = __float2bfloat16(v.z);
        g_WT[(size_t)(f + 3) * INF + k] = __float2bfloat16(v.w);
    } else {                           // zero Wh1/Wh2 (atomicAdd targets; every replay)
#pragma unroll
        for (int u = 0; u < 32; u++) { g_Wh1[u * 256 + t] = 0.f; g_Wh2[u * 256 + t] = 0.f; }
    }
}

// ================= K1: Wh = h @ W via mma.sync, + Wh1/Wh2 =================
// 128 CTAs x 64 rows. Warp tile 16 rows x 64 feats.
#define GSA 0u
#define GSB 16384u
#define GSV 49152u
#define GSM (49152 + 1024 + 128)

__device__ __forceinline__ void gemm_issue(uint32_t sb, int i0, int ko, int t) {
    const uint32_t abuf = sb + GSA + (uint32_t)(ko & 1) * 8192u;
    const uint32_t bbuf = sb + GSB + (uint32_t)(ko & 1) * 16384u;
#pragma unroll
    for (int s = 0; s < 2; s++) {      // A: 512 chunks
        int c = t + s * 256;
        int r = c >> 3, u = c & 7;
        cp16(abuf + (uint32_t)r * 128u + (((uint32_t)u * 16u) ^ ((uint32_t)(r & 7) << 4)),
             &g_hb[(size_t)(i0 + r) * INF + ko * 64 + u * 8]);
    }
#pragma unroll
    for (int s = 0; s < 4; s++) {      // B: 1024 chunks
        int c = t + s * 256;
        int f = c >> 3, u = c & 7;
        cp16(bbuf + (uint32_t)f * 128u + (((uint32_t)u * 16u) ^ ((uint32_t)(f & 7) << 4)),
             &g_WT[(size_t)f * INF + ko * 64 + u * 8]);
    }
    asm volatile("cp.async.commit_group;" ::: "memory");
}

__global__ void __launch_bounds__(256, 1) k_gemm(const float* __restrict__ a) {
    extern __shared__ char dsm[];
    uint32_t sb = (uint32_t)__cvta_generic_to_shared(dsm);
    sb = (sb + 127u) & ~127u;

    const int t = threadIdx.x, w = t >> 5, l = t & 31;
    const int i0 = blockIdx.x * 64;
    const int m0 = (w >> 1) * 16, n0 = (w & 1) * 64;

    if (t < 256) sts32f(sb + GSV + (uint32_t)t * 4u, a[t]);   // a1|a2 (256 floats)

    gemm_issue(sb, i0, 0, t);

    const int q = l >> 3, lq = l & 7;
    const uint32_t keyL = (uint32_t)lq << 4;
    const int arow = m0 + (q & 1) * 8 + lq;
    const uint32_t paA = (uint32_t)arow * 128u;
    const uint32_t offA = ((uint32_t)(q >> 1) * 16u);
    const int bq_f = (q >> 1) * 8 + lq;          // feat-within-16 for B ldsm
    const uint32_t offBk = ((uint32_t)(q & 1) * 16u);

    float acc[8][4];
#pragma unroll
    for (int nt = 0; nt < 8; nt++)
#pragma unroll
        for (int c = 0; c < 4; c++) acc[nt][c] = 0.f;

#pragma unroll 1
    for (int ko = 0; ko < 8; ko++) {
        asm volatile("cp.async.wait_group 0;" ::: "memory");
        __syncthreads();
        if (ko < 7) gemm_issue(sb, i0, ko + 1, t);

        const uint32_t abuf = sb + GSA + (uint32_t)(ko & 1) * 8192u;
        const uint32_t bbuf = sb + GSB + (uint32_t)(ko & 1) * 16384u;
#pragma unroll
        for (int kk = 0; kk < 4; kk++) {
            uint32_t af[4];
            ldsm4(af, abuf + paA + (((uint32_t)kk * 32u + offA) ^ keyL));
            uint32_t bfr[4][4];
#pragma unroll
            for (int i = 0; i < 4; i++) {
                int f = n0 + i * 16 + bq_f;
                ldsm4(bfr[i], bbuf + (uint32_t)f * 128u
                              + (((uint32_t)kk * 32u + offBk) ^ ((uint32_t)(f & 7) << 4)));
            }
#pragma unroll
            for (int nt = 0; nt < 8; nt++)
                mma16816(acc[nt], af, bfr[nt >> 1][(nt & 1) * 2], bfr[nt >> 1][(nt & 1) * 2 + 1]);
        }
        __syncthreads();
    }

    // epilogue: WhT bf16 scattered stores + Wh1/Wh2 row-dots
    float w1a = 0.f, w1b = 0.f, w2a = 0.f, w2b = 0.f;
#pragma unroll
    for (int nt = 0; nt < 8; nt++)
#pragma unroll
        for (int c = 0; c < 4; c++) {
            int feat = n0 + nt * 8 + (l & 3) * 2 + (c & 1);
            int row = i0 + m0 + (l >> 2) + (c >> 1) * 8;
            float v = acc[nt][c];
            g_WhT[(size_t)feat * NN + row] = __float2bfloat16(v);
            float av1 = lds32f(sb + GSV + (uint32_t)feat * 4u);
            float av2 = lds32f(sb + GSV + (uint32_t)(128 + feat) * 4u);
            if ((c >> 1) == 0) { w1a = fmaf(v, av1, w1a); w2a = fmaf(v, av2, w2a); }
            else               { w1b = fmaf(v, av1, w1b); w2b = fmaf(v, av2, w2b); }
        }
#pragma unroll
    for (int s = 1; s <= 2; s <<= 1) {
        w1a += __shfl_xor_sync(0xffffffffu, w1a, s);
        w1b += __shfl_xor_sync(0xffffffffu, w1b, s);
        w2a += __shfl_xor_sync(0xffffffffu, w2a, s);
        w2b += __shfl_xor_sync(0xffffffffu, w2b, s);
    }
    if ((l & 3) == 0) {
        int r0 = i0 + m0 + (l >> 2);
        atomicAdd(&g_Wh1[r0], w1a);     atomicAdd(&g_Wh2[r0], w2a);
        atomicAdd(&g_Wh1[r0 + 8], w1b); atomicAdd(&g_Wh2[r0 + 8], w2b);
    }
}

// ================= K2: fused masked-softmax attention via mma.sync =================
// CTA: 128 rows x 4096 j. adj via register LDG prefetch; P single-buffer; B double.
// One __syncthreads + one pair-scoped bar per tile.

#define SP    0u
#define SB0   32768u
#define SWH2  98304u
#define SM_DYN (98304 + 16384 + 128)

__device__ __forceinline__ void issue_B(uint32_t sb, const __nv_bfloat16* whg, int t, int tt) {
    const int bf = t >> 1, bh = t & 1;
    const uint32_t bbase = sb + SB0 + (uint32_t)(tt & 1) * 32768u
        + (uint32_t)((bf >> 3) + bh * 16) * 1024u + (uint32_t)(bf & 7) * 128u;
    const uint32_t bkey = (uint32_t)(bf & 7) << 4;
    const __nv_bfloat16* bs = whg + (size_t)bf * NN + tt * 128 + bh * 64;
#pragma unroll
    for (int c = 0; c < 8; c++)
        cp16(bbase + (((uint32_t)c * 16u) ^ bkey), bs + c * 8);
    asm volatile("cp.async.commit_group;" ::: "memory");
}

__global__ void __launch_bounds__(256, 1) k_attn(const int* __restrict__ adj) {
    extern __shared__ char dsm[];
    uint32_t sb = (uint32_t)__cvta_generic_to_shared(dsm);
    sb = (sb + 127u) & ~127u;

    const int t = threadIdx.x, w = t >> 5, l = t & 31;
    const int rb = blockIdx.x >> 1, split = blockIdx.x & 1;
    const int i0 = rb * 128, jb = split * 4096;

    const __nv_bfloat16* whg = g_WhT + jb;

    // stage Wh2 for this j-range
    for (int x = t; x < 4096; x += 256) sts32f(sb + SWH2 + (uint32_t)x * 4u, g_Wh2[jb + x]);

    issue_B(sb, whg, t, 0);

    const int pairid = w >> 1;
    const int rbase = pairid * 32 + (w & 1) * 16;   // build rows = own pair's MMA rows
    float wh1r[16];
#pragma unroll
    for (int r = 0; r < 16; r++) wh1r[r] = g_Wh1[i0 + rbase + r];

    const int* adjbase = adj + (size_t)(i0 + rbase) * NN + jb + l * 4;
    int4 ar[16];
#pragma unroll
    for (int u = 0; u < 16; u++) ar[u] = *reinterpret_cast<const int4*>(adjbase + (size_t)u * NN);

    // MMA constants (proven R3 mappings): m0 = pair rows, n0 = feat half
    const int m0 = pairid * 32, n0 = (w & 1) * 64;
    const int q = l >> 3, lq = l & 7;
    const int arow = m0 + (q & 1) * 8 + lq;
    const int acolb = (q >> 1) * 8;
    const uint32_t paA = ((uint32_t)(arow >> 3) << 10) + ((uint32_t)(arow & 7) << 7);
    const uint32_t keyA = (uint32_t)(arow & 7) << 4;
    const int bfeat = n0 + (q >> 1) * 8 + lq;
    const int bcolb = (q & 1) * 8;
    const uint32_t paB = ((uint32_t)(bfeat >> 3) << 10) + ((uint32_t)(bfeat & 7) << 7);
    const uint32_t keyB = (uint32_t)(bfeat & 7) << 4;

    float acc[2][8][4];
#pragma unroll
    for (int mt = 0; mt < 2; mt++)
#pragma unroll
        for (int nt = 0; nt < 8; nt++)
#pragma unroll
            for (int c = 0; c < 4; c++) acc[mt][nt][c] = 0.f;
    float dden[16];
#pragma unroll
    for (int r = 0; r < 16; r++) dden[r] = 0.f;

#pragma unroll 1
    for (int tt = 0; tt < 32; tt++) {
        asm volatile("cp.async.wait_group 0;" ::: "memory");
        __syncthreads();               // B(tt) visible; all mma(tt-1) done (P + B bufs free)
        if (tt < 31) issue_B(sb, whg, t, tt + 1);

        // ---- build P rows [rbase, rbase+16) from adj regs ----
        {
            float4 w2 = lds128f(sb + SWH2 + (uint32_t)(tt * 128 + l * 4) * 4u);
#pragma unroll
            for (int r = 0; r < 16; r++) {
                int row = rbase + r;
                float wh1v = wh1r[r];
                int4 a4 = ar[r];
                float x0 = wh1v + w2.x, x1 = wh1v + w2.y, x2 = wh1v + w2.z, x3 = wh1v + w2.w;
                float p0 = a4.x ? __expf(fmaxf(x0, 0.2f * x0)) : 0.f;
                float p1 = a4.y ? __expf(fmaxf(x1, 0.2f * x1)) : 0.f;
                float p2 = a4.z ? __expf(fmaxf(x2, 0.2f * x2)) : 0.f;
                float p3 = a4.w ? __expf(fmaxf(x3, 0.2f * x3)) : 0.f;
                dden[r] += (p0 + p1) + (p2 + p3);
                uint32_t paddr = sb + SP
                    + (uint32_t)(((row >> 3) + ((l >> 4) << 4)) * 1024 + (row & 7) * 128)
                    + (((uint32_t)(l & 15) * 8u) ^ ((uint32_t)(row & 7) << 4));
                sts64(paddr, pack2(p0, p1), pack2(p2, p3));
            }
        }
        // prefetch adj(tt+1) into regs (lands under the MMA phase)
        if (tt < 31) {
            const int* nb = adjbase + (tt + 1) * 128;
#pragma unroll
            for (int u = 0; u < 16; u++) ar[u] = *reinterpret_cast<const int4*>(nb + (size_t)u * NN);
        }

        asm volatile("bar.sync %0, 64;" :: "r"(1 + pairid) : "memory");  // pair rendezvous

        // ---- mma phase ----
        {
            const uint32_t sB = sb + SB0 + (uint32_t)(tt & 1) * 32768u;
#pragma unroll
            for (int kk = 0; kk < 8; kk++) {
                int colA = kk * 16 + acolb;
                uint32_t aA = sb + SP + paA + (uint32_t)((colA >> 6) << 14)
                            + ((uint32_t)((colA & 63) << 1) ^ keyA);
                uint32_t af0[4], af1[4];
                ldsm4(af0, aA);
                ldsm4(af1, aA + 2048u);
                int colB = kk * 16 + bcolb;
                uint32_t aB = sB + paB + (uint32_t)((colB >> 6) << 14)
                            + ((uint32_t)((colB & 63) << 1) ^ keyB);
                uint32_t bfr[4][4];
                ldsm4(bfr[0], aB);
                ldsm4(bfr[1], aB + 2048u);
                ldsm4(bfr[2], aB + 4096u);
                ldsm4(bfr[3], aB + 6144u);
#pragma unroll
                for (int nt = 0; nt < 8; nt++) {
                    uint32_t b0 = bfr[nt >> 1][(nt & 1) * 2];
                    uint32_t b1 = bfr[nt >> 1][(nt & 1) * 2 + 1];
                    mma16816(acc[0][nt], af0, b0, b1);
                    mma16816(acc[1][nt], af1, b0, b1);
                }
            }
        }
    }

    // ---- den: reduce lanes per build-row ----
#pragma unroll
    for (int r = 0; r < 16; r++) {
        float v = dden[r];
        v += __shfl_xor_sync(0xffffffffu, v, 16);
        v += __shfl_xor_sync(0xffffffffu, v, 8);
        v += __shfl_xor_sync(0xffffffffu, v, 4);
        v += __shfl_xor_sync(0xffffffffu, v, 2);
        v += __shfl_xor_sync(0xffffffffu, v, 1);
        if (l == 0) g_den[split * NN + i0 + rbase + r] = v;
    }

    // ---- num epilogue ----
#pragma unroll
    for (int mt = 0; mt < 2; mt++)
#pragma unroll
        for (int nt = 0; nt < 8; nt++) {
            int row = i0 + m0 + mt * 16 + (l >> 2);
            int feat = n0 + nt * 8 + (l & 3) * 2;
            float* b = &g_num[((size_t)split * NN + row) * OF + feat];
            b[0] = acc[mt][nt][0];
            b[1] = acc[mt][nt][1];
            b[8 * OF] = acc[mt][nt][2];
            b[8 * OF + 1] = acc[mt][nt][3];
        }
}

// ================= K3: combine splits, finalize =================
__global__ __launch_bounds__(256) void k_final(const float* __restrict__ rnd,
                                               float* __restrict__ out) {
    int idx = blockIdx.x * 256 + threadIdx.x;
    int i = idx >> 7;
    float num = g_num[idx] + g_num[(size_t)NN * OF + idx];
    float den = g_den[i] + g_den[NN + i];
    float v = (num / den + rnd[idx]) * 1e-5f;
    out[idx] = v > 0.f ? v : expm1f(v);
}

// ================= launch =================
extern "C" void kernel_launch(void* const* d_in, const int* in_sizes, int n_in,
                              void* d_out, int out_size) {
    const float* h   = (const float*)d_in[0];
    const int*   adj = (const int*)d_in[1];
    const float* W   = (const float*)d_in[2];
    const float* a   = (const float*)d_in[3];
    const float* rnd = (const float*)d_in[4];
    float* out = (float*)d_out;

    cudaFuncSetAttribute(k_gemm, cudaFuncAttributeMaxDynamicSharedMemorySize, GSM);
    cudaFuncSetAttribute(k_attn, cudaFuncAttributeMaxDynamicSharedMemorySize, SM_DYN);

    k_prep<<<1089, 256>>>(h, W);
    k_gemm<<<128, 256, GSM>>>(a);
    k_attn<<<128, 256, SM_DYN>>>(adj);
    k_final<<<4096, 256>>>(rnd, out);
}

// round 6
// speedup vs baseline: 1.3481x; 1.1172x over previous
#include <cuda_runtime.h>
#include <cuda_bf16.h>
#include <cstdint>

#define NN 8192
#define INF 512
#define OF 128

// ---------------- scratch (device globals; no allocation) ----------------
__device__ __nv_bfloat16 g_hb[(size_t)NN * INF];   // h in bf16 [node][k]
__device__ __nv_bfloat16 g_WT[(size_t)OF * INF];   // W^T bf16 [feat][k]
__device__ __nv_bfloat16 g_WhT[(size_t)OF * NN];   // [feat][node] bf16
__device__ float g_Wh1[NN];
__device__ float g_Wh2[NN];
__device__ float g_num[(size_t)2 * NN * OF];       // [split][node][feat]
__device__ float g_den[2 * NN];                    // [split][node]

// ---------------- helpers ----------------
__device__ __forceinline__ uint32_t pack2(float lo, float hi) {
    uint32_t r;
    asm("cvt.rn.bf16x2.f32 %0, %1, %2;" : "=r"(r) : "f"(hi), "f"(lo));
    return r;
}
__device__ __forceinline__ void sts64(uint32_t a, uint32_t x, uint32_t y) {
    asm volatile("st.shared.v2.b32 [%0], {%1,%2};" :: "r"(a), "r"(x), "r"(y) : "memory");
}
__device__ __forceinline__ void sts32f(uint32_t a, float v) {
    asm volatile("st.shared.f32 [%0], %1;" :: "r"(a), "f"(v) : "memory");
}
__device__ __forceinline__ float lds32f(uint32_t a) {
    float v; asm volatile("ld.shared.f32 %0, [%1];" : "=f"(v) : "r"(a)); return v;
}
__device__ __forceinline__ float4 lds128f(uint32_t a) {
    float4 v;
    asm volatile("ld.shared.v4.f32 {%0,%1,%2,%3}, [%4];"
                 : "=f"(v.x), "=f"(v.y), "=f"(v.z), "=f"(v.w) : "r"(a));
    return v;
}
__device__ __forceinline__ void ldsm4(uint32_t* r, uint32_t a) {
    asm volatile("ldmatrix.sync.aligned.m8n8.x4.shared.b16 {%0,%1,%2,%3}, [%4];"
                 : "=r"(r[0]), "=r"(r[1]), "=r"(r[2]), "=r"(r[3]) : "r"(a));
}
__device__ __forceinline__ void mma16816(float* d, const uint32_t* a, uint32_t b0, uint32_t b1) {
    asm volatile(
        "mma.sync.aligned.m16n8k16.row.col.f32.bf16.bf16.f32 "
        "{%0,%1,%2,%3}, {%4,%5,%6,%7}, {%8,%9}, {%0,%1,%2,%3};"
        : "+f"(d[0]), "+f"(d[1]), "+f"(d[2]), "+f"(d[3])
        : "r"(a[0]), "r"(a[1]), "r"(a[2]), "r"(a[3]), "r"(b0), "r"(b1));
}
__device__ __forceinline__ void cp16(uint32_t s, const void* g) {
    asm volatile("cp.async.cg.shared.global [%0], [%1], 16;" :: "r"(s), "l"(g) : "memory");
}

// ================= K0: prep — h->bf16, W->W^T bf16, zero Wh1/Wh2 =================
__global__ __launch_bounds__(256) void k_prep(const float* __restrict__ h,
                                              const float* __restrict__ W) {
    const int b = blockIdx.x, t = threadIdx.x;
    if (b < 1024) {                    // h convert: 1024 CTAs x 1024 float4
#pragma unroll
        for (int u = 0; u < 4; u++) {
            size_t i4 = (size_t)b * 1024 + u * 256 + t;
            float4 v = reinterpret_cast<const float4*>(h)[i4];
            uint2 p = make_uint2(pack2(v.x, v.y), pack2(v.z, v.w));
            *reinterpret_cast<uint2*>(&g_hb[i4 * 4]) = p;
        }
    } else if (b < 1088) {             // W transpose: 64 CTAs x 1024 elems
        int idx = (b - 1024) * 1024 + t * 4;
        int k = idx >> 7, f = idx & 127;
        float4 v = *reinterpret_cast<const float4*>(&W[(size_t)k * OF + f]);
        g_WT[(size_t)(f + 0) * INF + k] = __float2bfloat16(v.x);
        g_WT[(size_t)(f + 1) * INF + k] = __float2bfloat16(v.y);
        g_WT[(size_t)(f + 2) * INF + k] = __float2bfloat16(v.z);
        g_WT[(size_t)(f + 3) * INF + k] = __float2bfloat16(v.w);
    } else {                           // zero Wh1/Wh2 (atomicAdd targets; every replay)
#pragma unroll
        for (int u = 0; u < 32; u++) { g_Wh1[u * 256 + t] = 0.f; g_Wh2[u * 256 + t] = 0.f; }
    }
}

// ================= K1: Wh = h @ W via mma.sync, + Wh1/Wh2 =================
#define GSA 0u
#define GSB 16384u
#define GSV 49152u
#define GSM (49152 + 1024 + 128)

__device__ __forceinline__ void gemm_issue(uint32_t sb, int i0, int ko, int t) {
    const uint32_t abuf = sb + GSA + (uint32_t)(ko & 1) * 8192u;
    const uint32_t bbuf = sb + GSB + (uint32_t)(ko & 1) * 16384u;
#pragma unroll
    for (int s = 0; s < 2; s++) {
        int c = t + s * 256;
        int r = c >> 3, u = c & 7;
        cp16(abuf + (uint32_t)r * 128u + (((uint32_t)u * 16u) ^ ((uint32_t)(r & 7) << 4)),
             &g_hb[(size_t)(i0 + r) * INF + ko * 64 + u * 8]);
    }
#pragma unroll
    for (int s = 0; s < 4; s++) {
        int c = t + s * 256;
        int f = c >> 3, u = c & 7;
        cp16(bbuf + (uint32_t)f * 128u + (((uint32_t)u * 16u) ^ ((uint32_t)(f & 7) << 4)),
             &g_WT[(size_t)f * INF + ko * 64 + u * 8]);
    }
    asm volatile("cp.async.commit_group;" ::: "memory");
}

__global__ void __launch_bounds__(256, 1) k_gemm(const float* __restrict__ a) {
    extern __shared__ char dsm[];
    uint32_t sb = (uint32_t)__cvta_generic_to_shared(dsm);
    sb = (sb + 127u) & ~127u;

    const int t = threadIdx.x, w = t >> 5, l = t & 31;
    const int i0 = blockIdx.x * 64;
    const int m0 = (w >> 1) * 16, n0 = (w & 1) * 64;

    if (t < 256) sts32f(sb + GSV + (uint32_t)t * 4u, a[t]);

    gemm_issue(sb, i0, 0, t);

    const int q = l >> 3, lq = l & 7;
    const uint32_t keyL = (uint32_t)lq << 4;
    const int arow = m0 + (q & 1) * 8 + lq;
    const uint32_t paA = (uint32_t)arow * 128u;
    const uint32_t offA = ((uint32_t)(q >> 1) * 16u);
    const int bq_f = (q >> 1) * 8 + lq;
    const uint32_t offBk = ((uint32_t)(q & 1) * 16u);

    float acc[8][4];
#pragma unroll
    for (int nt = 0; nt < 8; nt++)
#pragma unroll
        for (int c = 0; c < 4; c++) acc[nt][c] = 0.f;

#pragma unroll 1
    for (int ko = 0; ko < 8; ko++) {
        asm volatile("cp.async.wait_group 0;" ::: "memory");
        __syncthreads();
        if (ko < 7) gemm_issue(sb, i0, ko + 1, t);

        const uint32_t abuf = sb + GSA + (uint32_t)(ko & 1) * 8192u;
        const uint32_t bbuf = sb + GSB + (uint32_t)(ko & 1) * 16384u;
#pragma unroll
        for (int kk = 0; kk < 4; kk++) {
            uint32_t af[4];
            ldsm4(af, abuf + paA + (((uint32_t)kk * 32u + offA) ^ keyL));
            uint32_t bfr[4][4];
#pragma unroll
            for (int i = 0; i < 4; i++) {
                int f = n0 + i * 16 + bq_f;
                ldsm4(bfr[i], bbuf + (uint32_t)f * 128u
                              + (((uint32_t)kk * 32u + offBk) ^ ((uint32_t)(f & 7) << 4)));
            }
#pragma unroll
            for (int nt = 0; nt < 8; nt++)
                mma16816(acc[nt], af, bfr[nt >> 1][(nt & 1) * 2], bfr[nt >> 1][(nt & 1) * 2 + 1]);
        }
        __syncthreads();
    }

    float w1a = 0.f, w1b = 0.f, w2a = 0.f, w2b = 0.f;
#pragma unroll
    for (int nt = 0; nt < 8; nt++)
#pragma unroll
        for (int c = 0; c < 4; c++) {
            int feat = n0 + nt * 8 + (l & 3) * 2 + (c & 1);
            int row = i0 + m0 + (l >> 2) + (c >> 1) * 8;
            float v = acc[nt][c];
            g_WhT[(size_t)feat * NN + row] = __float2bfloat16(v);
            float av1 = lds32f(sb + GSV + (uint32_t)feat * 4u);
            float av2 = lds32f(sb + GSV + (uint32_t)(128 + feat) * 4u);
            if ((c >> 1) == 0) { w1a = fmaf(v, av1, w1a); w2a = fmaf(v, av2, w2a); }
            else               { w1b = fmaf(v, av1, w1b); w2b = fmaf(v, av2, w2b); }
        }
#pragma unroll
    for (int s = 1; s <= 2; s <<= 1) {
        w1a += __shfl_xor_sync(0xffffffffu, w1a, s);
        w1b += __shfl_xor_sync(0xffffffffu, w1b, s);
        w2a += __shfl_xor_sync(0xffffffffu, w2a, s);
        w2b += __shfl_xor_sync(0xffffffffu, w2b, s);
    }
    if ((l & 3) == 0) {
        int r0 = i0 + m0 + (l >> 2);
        atomicAdd(&g_Wh1[r0], w1a);     atomicAdd(&g_Wh2[r0], w2a);
        atomicAdd(&g_Wh1[r0 + 8], w1b); atomicAdd(&g_Wh2[r0 + 8], w2b);
    }
}

// ================= K2: fused attention — build(tt+1) interleaved into mma(tt) =================
// P double-buffered; one __syncthreads per tile; adj prefetch folded per-row.

#define SP0   0u
#define SB0   65536u
#define SWH2  131072u
#define SM_DYN (131072 + 16384 + 256)

__device__ __forceinline__ void issue_B(uint32_t sb, const __nv_bfloat16* whg, int t, int tt) {
    const int bf = t >> 1, bh = t & 1;
    const uint32_t bbase = sb + SB0 + (uint32_t)(tt & 1) * 32768u
        + (uint32_t)((bf >> 3) + bh * 16) * 1024u + (uint32_t)(bf & 7) * 128u;
    const uint32_t bkey = (uint32_t)(bf & 7) << 4;
    const __nv_bfloat16* bs = whg + (size_t)bf * NN + tt * 128 + bh * 64;
#pragma unroll
    for (int c = 0; c < 8; c++)
        cp16(bbase + (((uint32_t)c * 16u) ^ bkey), bs + c * 8);
    asm volatile("cp.async.commit_group;" ::: "memory");
}

__global__ void __launch_bounds__(256, 1) k_attn(const int* __restrict__ adj) {
    extern __shared__ char dsm[];
    uint32_t sb = (uint32_t)__cvta_generic_to_shared(dsm);
    sb = (sb + 127u) & ~127u;

    const int t = threadIdx.x, w = t >> 5, l = t & 31;
    const int rb = blockIdx.x >> 1, split = blockIdx.x & 1;
    const int i0 = rb * 128, jb = split * 4096;

    const __nv_bfloat16* whg = g_WhT + jb;

    for (int x = t; x < 4096; x += 256) sts32f(sb + SWH2 + (uint32_t)x * 4u, g_Wh2[jb + x]);

    issue_B(sb, whg, t, 0);

    const int pairid = w >> 1;
    const int rbase = pairid * 32 + (w & 1) * 16;
    float wh1r[16];
#pragma unroll
    for (int r = 0; r < 16; r++) wh1r[r] = g_Wh1[i0 + rbase + r];

    const int* adjbase = adj + (size_t)(i0 + rbase) * NN + jb + l * 4;
    int4 ar[16];
#pragma unroll
    for (int u = 0; u < 16; u++) ar[u] = *reinterpret_cast<const int4*>(adjbase + (size_t)u * NN);

    const int m0 = pairid * 32, n0 = (w & 1) * 64;
    const int q = l >> 3, lq = l & 7;
    const int arow = m0 + (q & 1) * 8 + lq;
    const int acolb = (q >> 1) * 8;
    const uint32_t paA = ((uint32_t)(arow >> 3) << 10) + ((uint32_t)(arow & 7) << 7);
    const uint32_t keyA = (uint32_t)(arow & 7) << 4;
    const int bfeat = n0 + (q >> 1) * 8 + lq;
    const int bcolb = (q & 1) * 8;
    const uint32_t paB = ((uint32_t)(bfeat >> 3) << 10) + ((uint32_t)(bfeat & 7) << 7);
    const uint32_t keyB = (uint32_t)(bfeat & 7) << 4;

    // per-thread P store address pieces (row varies)
    const uint32_t pst_col = (uint32_t)((l >> 4) << 4) * 1024u;
    const uint32_t pst_j   = (uint32_t)(l & 15) * 8u;

    float acc[2][8][4];
#pragma unroll
    for (int mt = 0; mt < 2; mt++)
#pragma unroll
        for (int nt = 0; nt < 8; nt++)
#pragma unroll
            for (int c = 0; c < 4; c++) acc[mt][nt][c] = 0.f;
    float dden[16];
#pragma unroll
    for (int r = 0; r < 16; r++) dden[r] = 0.f;

    __syncthreads();   // Wh2 staged

    // ---- prologue: build P(0) into buf0, prefetch adj(1) ----
    {
        float4 w2 = lds128f(sb + SWH2 + (uint32_t)(l * 4) * 4u);
        const int* nb = adjbase + 128;
#pragma unroll
        for (int r = 0; r < 16; r++) {
            int row = rbase + r;
            float wh1v = wh1r[r];
            int4 a4 = ar[r];
            float x0 = wh1v + w2.x, x1 = wh1v + w2.y, x2 = wh1v + w2.z, x3 = wh1v + w2.w;
            float p0 = a4.x ? __expf(fmaxf(x0, 0.2f * x0)) : 0.f;
            float p1 = a4.y ? __expf(fmaxf(x1, 0.2f * x1)) : 0.f;
            float p2 = a4.z ? __expf(fmaxf(x2, 0.2f * x2)) : 0.f;
            float p3 = a4.w ? __expf(fmaxf(x3, 0.2f * x3)) : 0.f;
            dden[r] += (p0 + p1) + (p2 + p3);
            uint32_t paddr = sb + SP0 + pst_col
                + (uint32_t)(((row >> 3) & 1) * 1024 + (row & 7) * 128)
                + (pst_j ^ ((uint32_t)(row & 7) << 4))
                + (uint32_t)((row >> 4) << 11);
            sts64(paddr, pack2(p0, p1), pack2(p2, p3));
            ar[r] = *reinterpret_cast<const int4*>(nb + (size_t)r * NN);
        }
    }

#pragma unroll 1
    for (int tt = 0; tt < 32; tt++) {
        asm volatile("cp.async.wait_group 0;" ::: "memory");
        __syncthreads();               // B(tt) + P(tt) visible; old bufs free
        if (tt < 31) issue_B(sb, whg, t, tt + 1);

        const uint32_t sA  = sb + SP0 + (uint32_t)(tt & 1) * 32768u;
        const uint32_t sPn = sb + SP0 + (uint32_t)((tt + 1) & 1) * 32768u;
        const uint32_t sB  = sb + SB0 + (uint32_t)(tt & 1) * 32768u;

        float4 w2;
        if (tt < 31) w2 = lds128f(sb + SWH2 + (uint32_t)((tt + 1) * 128 + l * 4) * 4u);
        const int* nb = adjbase + (tt + 2) * 128;

#pragma unroll
        for (int kk = 0; kk < 8; kk++) {
            // ---- mma chunk (reads P(tt), B(tt)) ----
            int colA = kk * 16 + acolb;
            uint32_t aA = sA + paA + (uint32_t)((colA >> 6) << 14)
                        + ((uint32_t)((colA & 63) << 1) ^ keyA);
            uint32_t af0[4], af1[4];
            ldsm4(af0, aA);
            ldsm4(af1, aA + 2048u);
            int colB = kk * 16 + bcolb;
            uint32_t aB = sB + paB + (uint32_t)((colB >> 6) << 14)
                        + ((uint32_t)((colB & 63) << 1) ^ keyB);
            uint32_t bfr[4][4];
            ldsm4(bfr[0], aB);
            ldsm4(bfr[1], aB + 2048u);
            ldsm4(bfr[2], aB + 4096u);
            ldsm4(bfr[3], aB + 6144u);
#pragma unroll
            for (int nt = 0; nt < 8; nt++) {
                uint32_t b0 = bfr[nt >> 1][(nt & 1) * 2];
                uint32_t b1 = bfr[nt >> 1][(nt & 1) * 2 + 1];
                mma16816(acc[0][nt], af0, b0, b1);
                mma16816(acc[1][nt], af1, b0, b1);
            }
            // ---- build 2 rows of P(tt+1), prefetch adj(tt+2) ----
            if (tt < 31) {
#pragma unroll
                for (int rr = 0; rr < 2; rr++) {
                    int r = kk * 2 + rr;
                    int row = rbase + r;
                    float wh1v = wh1r[r];
                    int4 a4 = ar[r];
                    float x0 = wh1v + w2.x, x1 = wh1v + w2.y, x2 = wh1v + w2.z, x3 = wh1v + w2.w;
                    float p0 = a4.x ? __expf(fmaxf(x0, 0.2f * x0)) : 0.f;
                    float p1 = a4.y ? __expf(fmaxf(x1, 0.2f * x1)) : 0.f;
                    float p2 = a4.z ? __expf(fmaxf(x2, 0.2f * x2)) : 0.f;
                    float p3 = a4.w ? __expf(fmaxf(x3, 0.2f * x3)) : 0.f;
                    dden[r] += (p0 + p1) + (p2 + p3);
                    uint32_t paddr = sPn + pst_col
                        + (uint32_t)(((row >> 3) & 1) * 1024 + (row & 7) * 128)
                        + (pst_j ^ ((uint32_t)(row & 7) << 4))
                        + (uint32_t)((row >> 4) << 11);
                    sts64(paddr, pack2(p0, p1), pack2(p2, p3));
                    if (tt <= 29) ar[r] = *reinterpret_cast<const int4*>(nb + (size_t)r * NN);
                }
            }
        }
    }

    // ---- den: reduce lanes per build-row ----
#pragma unroll
    for (int r = 0; r < 16; r++) {
        float v = dden[r];
        v += __shfl_xor_sync(0xffffffffu, v, 16);
        v += __shfl_xor_sync(0xffffffffu, v, 8);
        v += __shfl_xor_sync(0xffffffffu, v, 4);
        v += __shfl_xor_sync(0xffffffffu, v, 2);
        v += __shfl_xor_sync(0xffffffffu, v, 1);
        if (l == 0) g_den[split * NN + i0 + rbase + r] = v;
    }

    // ---- num epilogue ----
#pragma unroll
    for (int mt = 0; mt < 2; mt++)
#pragma unroll
        for (int nt = 0; nt < 8; nt++) {
            int row = i0 + m0 + mt * 16 + (l >> 2);
            int feat = n0 + nt * 8 + (l & 3) * 2;
            float* b = &g_num[((size_t)split * NN + row) * OF + feat];
            b[0] = acc[mt][nt][0];
            b[1] = acc[mt][nt][1];
            b[8 * OF] = acc[mt][nt][2];
            b[8 * OF + 1] = acc[mt][nt][3];
        }
}

// ================= K3: combine splits, finalize =================
__global__ __launch_bounds__(256) void k_final(const float* __restrict__ rnd,
                                               float* __restrict__ out) {
    int idx = blockIdx.x * 256 + threadIdx.x;
    int i = idx >> 7;
    float num = g_num[idx] + g_num[(size_t)NN * OF + idx];
    float den = g_den[i] + g_den[NN + i];
    float v = (num / den + rnd[idx]) * 1e-5f;
    out[idx] = v > 0.f ? v : expm1f(v);
}

// ================= launch =================
extern "C" void kernel_launch(void* const* d_in, const int* in_sizes, int n_in,
                              void* d_out, int out_size) {
    const float* h   = (const float*)d_in[0];
    const int*   adj = (const int*)d_in[1];
    const float* W   = (const float*)d_in[2];
    const float* a   = (const float*)d_in[3];
    const float* rnd = (const float*)d_in[4];
    float* out = (float*)d_out;

    cudaFuncSetAttribute(k_gemm, cudaFuncAttributeMaxDynamicSharedMemorySize, GSM);
    cudaFuncSetAttribute(k_attn, cudaFuncAttributeMaxDynamicSharedMemorySize, SM_DYN);

    k_prep<<<1089, 256>>>(h, W);
    k_gemm<<<128, 256, GSM>>>(a);
    k_attn<<<128, 256, SM_DYN>>>(adj);
    k_final<<<4096, 256>>>(rnd, out);
}